// round 11
// baseline (speedup 1.0000x reference)
#include <cuda_runtime.h>
#include <cuda_fp16.h>
#include <cstdint>
#include <math.h>

#define NROWS 131072
#define DDIM  64
#define KCB   512
#define TILE_M 256
#define NTILES (NROWS / TILE_M)     // 512
#define GRID_MAIN 148
#define THREADS 512

#define OFF_Q    0
#define OFF_LOSS (NROWS * DDIM)
#define OFF_PERP (OFF_LOSS + 1)
#define OFF_EMB  (OFF_PERP + 1)
#define OFF_IDX  (OFF_EMB + DDIM * KCB)

#define MARGIN 0.15625f
#define MASKH  0xFFFFFE00u
#define KEYBIAS 256.0f
#define SENT 0x7F7FFFFFu

__device__ float g_dw[DDIM * KCB];
__device__ float g_cluster[KCB];
__device__ float g_loss;
__device__ float g_enorm[KCB];
__device__ __align__(16) char g_xh[NROWS * DDIM * 2];   // x fp16, packed+swizzled
__device__ float g_xn[NROWS];                           // per-row ||x||^2

__device__ __forceinline__ uint32_t pb(uint32_t d) {
    return ((d >> 1) & 3u) * 32u + (d >> 4) * 8u + ((d >> 3) & 1u) * 4u + (d & 1u) * 2u;
}

// smem layout (bytes)
#define SO_EH    0u          // 65536
#define SO_EL    65536u      // 65536
#define SO_XH0   131072u     // 32768 (x tile buffer 0)
#define SO_XH1   163840u     // 32768 (x tile buffer 1)
#define SO_EN2   196608u     // 2048
#define SO_TOP   198656u     // 4096
#define SO_HIST  202752u     // 2048
#define SO_QUE   204800u     // 1024
#define SO_QUE2  205824u     // 1024
#define SO_QN    206848u     // 4
#define SO_QN2   206852u     // 4
#define SO_B64   206856u     // 8
#define SMEM_SZ  206864u

__device__ __forceinline__ void mma_f16(float* d, uint32_t a0, uint32_t a1,
                                        uint32_t a2, uint32_t a3,
                                        uint32_t b0, uint32_t b1) {
    asm volatile(
        "mma.sync.aligned.m16n8k16.row.col.f32.f16.f16.f32 "
        "{%0,%1,%2,%3}, {%4,%5,%6,%7}, {%8,%9}, {%0,%1,%2,%3};\n"
        : "+f"(d[0]), "+f"(d[1]), "+f"(d[2]), "+f"(d[3])
        : "r"(a0), "r"(a1), "r"(a2), "r"(a3), "r"(b0), "r"(b1));
}

__device__ __forceinline__ void ins3(uint32_t& m1, uint32_t& m2, uint32_t& m3,
                                     uint32_t k) {
    uint32_t h1 = max(m1, k); m1 = min(m1, k);
    uint32_t h2 = max(m2, h1); m2 = min(m2, h1);
    m3 = min(m3, h2);
}
__device__ __forceinline__ uint32_t mkkey(float dist, uint32_t n) {
    uint32_t r;
    asm("bfi.b32 %0, %1, %2, 0, 9;" : "=r"(r) : "r"(n), "r"(__float_as_uint(dist)));
    return r;
}
__device__ __forceinline__ void cp16(uint32_t dst, const void* src) {
    asm volatile("cp.async.cg.shared.global [%0], [%1], 16;"
                 :: "r"(dst), "l"(src) : "memory");
}

__device__ __forceinline__ void do_kb(
    const char* sm, int kb, int g, int q,
    const uint4& A0a, const uint4& A0b, const uint4& A1a, const uint4& A1b,
    const float* s_en2, uint32_t c0, uint32_t c1,
    uint32_t& m11, uint32_t& m12, uint32_t& m13,
    uint32_t& m21, uint32_t& m22, uint32_t& m23)
{
    float acc[8][4];
#pragma unroll
    for (int nt = 0; nt < 8; nt++)
#pragma unroll
        for (int j = 0; j < 4; j++) acc[nt][j] = 0.f;

#pragma unroll
    for (int nt = 0; nt < 8; nt++) {
        uint32_t rowb = (uint32_t)(kb * 64 + nt * 8 + g) * 128u;
        uint4 B0 = *(const uint4*)(sm + SO_EH + rowb + c0);
        uint4 B1 = *(const uint4*)(sm + SO_EH + rowb + c1);
        mma_f16(acc[nt], A0a.x, A1a.x, A0a.y, A1a.y, B0.x, B0.y);
        mma_f16(acc[nt], A0a.z, A1a.z, A0a.w, A1a.w, B0.z, B0.w);
        mma_f16(acc[nt], A0b.x, A1b.x, A0b.y, A1b.y, B1.x, B1.y);
        mma_f16(acc[nt], A0b.z, A1b.z, A0b.w, A1b.w, B1.z, B1.w);
    }
#pragma unroll
    for (int nt = 0; nt < 8; nt++) {
        uint32_t n0 = (uint32_t)(kb * 64 + nt * 8 + q * 2);
        float2 en = *(const float2*)&s_en2[n0];
        uint32_t k0 = mkkey(fmaf(-2.f, acc[nt][0], en.x), n0);
        uint32_t k1 = mkkey(fmaf(-2.f, acc[nt][1], en.y), n0 + 1);
        uint32_t k2 = mkkey(fmaf(-2.f, acc[nt][2], en.x), n0);
        uint32_t k3 = mkkey(fmaf(-2.f, acc[nt][3], en.y), n0 + 1);
        ins3(m11, m12, m13, k0);
        ins3(m11, m12, m13, k1);
        ins3(m21, m22, m23, k2);
        ins3(m21, m22, m23, k3);
    }
}

// ---------------------------------------------------------------------------
// Prep: exact ||e_k||^2 + zero small accumulators
// ---------------------------------------------------------------------------
__global__ void k_prep(const float* __restrict__ emb) {
    __shared__ float red[8][64];
    const int t = threadIdx.x, b = blockIdx.x;
    const int kk = t & 63, part = t >> 6;
    const int k = b * 64 + kk;
    float s = 0.f;
#pragma unroll
    for (int j = 0; j < 8; j++) {
        float e = emb[(part * 8 + j) * KCB + k];
        s = fmaf(e, e, s);
    }
    red[part][kk] = s;
    __syncthreads();
    if (t < 64) {
        float tot = red[0][t];
#pragma unroll
        for (int p = 1; p < 8; p++) tot += red[p][t];
        g_enorm[b * 64 + t] = tot;
    }
    if (b == 0) {
        g_cluster[t] = 0.f;
        if (t == 0) g_loss = 0.f;
    }
}

// Convert x -> fp16 packed/swizzled global buffer + per-row ||x||^2
__global__ __launch_bounds__(512)
void k_conv(const float* __restrict__ x) {
    const int tid = threadIdx.x;
#pragma unroll
    for (int j = 0; j < 4; j++) {
        int i = blockIdx.x * 2048 + j * 512 + tid;
        float4 v = ((const float4*)x)[i];
        uint32_t r = (uint32_t)i >> 4, c = ((uint32_t)i & 15u) * 4u;
        uint32_t xw = (r & 7u) * 16u;
        *(__half2*)(g_xh + (size_t)r * 128 + (pb(c) ^ xw)) =
            __floats2half2_rn(v.x, v.y);
        *(__half2*)(g_xh + (size_t)r * 128 + (pb(c + 2) ^ xw)) =
            __floats2half2_rn(v.z, v.w);
        float pn = fmaf(v.x, v.x, fmaf(v.y, v.y, fmaf(v.z, v.z, v.w * v.w)));
        pn += __shfl_xor_sync(0xffffffffu, pn, 1);
        pn += __shfl_xor_sync(0xffffffffu, pn, 2);
        pn += __shfl_xor_sync(0xffffffffu, pn, 4);
        pn += __shfl_xor_sync(0xffffffffu, pn, 8);
        if ((tid & 15) == 0) g_xn[r] = pn;
    }
}

__global__ void k_zero() { g_dw[blockIdx.x * 512 + threadIdx.x] = 0.f; }

// ---------------------------------------------------------------------------
// Main: persistent, cp.async double-buffered tiles
// ---------------------------------------------------------------------------
__global__ __launch_bounds__(THREADS, 1)
void k_main(const float* __restrict__ x, const float* __restrict__ emb,
            float* __restrict__ out_q, float* __restrict__ out_idx) {
    extern __shared__ __align__(1024) char sm[];
    const int tid  = threadIdx.x;
    const int wid  = tid >> 5;
    const int lane = tid & 31;
    const int g    = lane >> 5 ? 0 : (lane >> 2);   // lane>>2 (kept simple)
    const int q    = lane & 3;

    uint32_t SB = (uint32_t)__cvta_generic_to_shared(sm);

    float* s_en2  = (float*)(sm + SO_EN2);
    uint4* s_top  = (uint4*)(sm + SO_TOP);
    int*   s_hist = (int*)(sm + SO_HIST);
    int*   s_que  = (int*)(sm + SO_QUE);
    int*   s_que2 = (int*)(sm + SO_QUE2);
    int*   s_qn   = (int*)(sm + SO_QN);
    int*   s_qn2  = (int*)(sm + SO_QN2);
    unsigned long long* s_b64 = (unsigned long long*)(sm + SO_B64);

    // Stage embeddings (fp16 hi + residual)
    for (int i = tid; i < DDIM * KCB; i += THREADS) {
        uint32_t d = (uint32_t)i >> 9, k = (uint32_t)i & 511u;
        float e = emb[i];
        __half h = __float2half_rn(e);
        __half l = __float2half_rn(e - __half2float(h));
        uint32_t off = k * 128u + (pb(d) ^ ((k & 7u) * 16u));
        *(__half*)(sm + SO_EH + off) = h;
        *(__half*)(sm + SO_EL + off) = l;
    }
    s_en2[tid] = g_enorm[tid] + KEYBIAS;
    s_hist[tid] = 0;
    __syncthreads();

    const int r0 = wid * 16 + g;
    const int r1 = r0 + 8;
    const uint32_t c0 = ((uint32_t)q * 32u) ^ ((uint32_t)g * 16u);
    const uint32_t c1 = ((uint32_t)q * 32u + 16u) ^ ((uint32_t)g * 16u);

    float loss_acc = 0.f;

    // prefetch first tile into buffer 0
    {
        const char* src = g_xh + (size_t)blockIdx.x * 32768 + (size_t)tid * 16;
        uint32_t dst = SB + SO_XH0 + (uint32_t)tid * 16;
#pragma unroll
        for (int j = 0; j < 4; j++) cp16(dst + j * 8192, src + j * 8192);
        asm volatile("cp.async.commit_group;" ::: "memory");
    }
    int buf = 0;

    for (int tile = blockIdx.x; tile < NTILES; tile += gridDim.x) {
        // issue prefetch of next tile into other buffer (dummy refetch on last)
        {
            int nxt = tile + gridDim.x;
            int pf = nxt < NTILES ? nxt : tile;
            const char* src = g_xh + (size_t)pf * 32768 + (size_t)tid * 16;
            uint32_t dst = SB + (buf ? SO_XH0 : SO_XH1) + (uint32_t)tid * 16;
#pragma unroll
            for (int j = 0; j < 4; j++) cp16(dst + j * 8192, src + j * 8192);
            asm volatile("cp.async.commit_group;" ::: "memory");
        }
        // wait for CURRENT tile (leave 1 group = the prefetch just issued)
        asm volatile("cp.async.wait_group 1;" ::: "memory");
        if (tid == 0) { *s_qn = 0; *s_qn2 = 0; }
        __syncthreads();

        const uint32_t XB = buf ? SO_XH1 : SO_XH0;
        uint4 A0a = *(const uint4*)(sm + XB + (uint32_t)r0 * 128u + c0);
        uint4 A0b = *(const uint4*)(sm + XB + (uint32_t)r0 * 128u + c1);
        uint4 A1a = *(const uint4*)(sm + XB + (uint32_t)r1 * 128u + c0);
        uint4 A1b = *(const uint4*)(sm + XB + (uint32_t)r1 * 128u + c1);

        uint32_t e11 = SENT, e12 = SENT, e13 = SENT;
        uint32_t o11 = SENT, o12 = SENT, o13 = SENT;
        uint32_t e21 = SENT, e22 = SENT, e23 = SENT;
        uint32_t o21 = SENT, o22 = SENT, o23 = SENT;

#pragma unroll 1
        for (int kbp = 0; kbp < 4; kbp++) {
            do_kb(sm, 2 * kbp,     g, q, A0a, A0b, A1a, A1b, s_en2, c0, c1,
                  e11, e12, e13, e21, e22, e23);
            do_kb(sm, 2 * kbp + 1, g, q, A0a, A0b, A1a, A1b, s_en2, c0, c1,
                  o11, o12, o13, o21, o22, o23);
        }
        ins3(e11, e12, e13, o11); ins3(e11, e12, e13, o12); ins3(e11, e12, e13, o13);
        ins3(e21, e22, e23, o21); ins3(e21, e22, e23, o22); ins3(e21, e22, e23, o23);

#pragma unroll
        for (int o = 1; o <= 2; o <<= 1) {
            uint32_t q1 = __shfl_xor_sync(0xffffffffu, e11, o);
            uint32_t q2 = __shfl_xor_sync(0xffffffffu, e12, o);
            uint32_t q3 = __shfl_xor_sync(0xffffffffu, e13, o);
            ins3(e11, e12, e13, q1);
            ins3(e11, e12, e13, q2);
            ins3(e11, e12, e13, q3);
            q1 = __shfl_xor_sync(0xffffffffu, e21, o);
            q2 = __shfl_xor_sync(0xffffffffu, e22, o);
            q3 = __shfl_xor_sync(0xffffffffu, e23, o);
            ins3(e21, e22, e23, q1);
            ins3(e21, e22, e23, q2);
            ins3(e21, e22, e23, q3);
        }
        if (q == 0) {
            s_top[r0] = make_uint4(e11, e12, e13, 0u);
            s_top[r1] = make_uint4(e21, e22, e23, 0u);
        }
        __syncthreads();

        // ---- Phase A: uniform direct emission; queue hard rows ----
        {
            const int rloc = tid >> 1;
            const int half = tid & 1;
            const int row  = tile * TILE_M + rloc;
            uint4 K = s_top[rloc];
            float d1 = __uint_as_float(K.x & MASKH);
            float d2 = __uint_as_float(K.y & MASKH);
            float d3 = __uint_as_float(K.z & MASKH);
            int bidx = (int)(K.x & 511u);
            if (d2 - d1 >= MARGIN) {
                if (half == 0) {
                    out_idx[row] = (float)bidx;
                    atomicAdd(&s_hist[bidx], 1);
                    loss_acc += d1 - KEYBIAS + __ldg(&g_xn[row])
                              + __uint_as_float(K.x & 0xFF800000u) * 3.0517578125e-05f;
                }
                float* oq = out_q + (size_t)row * DDIM;
                uint32_t ebase = (uint32_t)bidx * 128u;
                uint32_t xe = ((uint32_t)bidx & 7u) * 16u;
#pragma unroll
                for (int d = half * 32; d < half * 32 + 32; d += 4) {
                    uint32_t oA = ebase + (pb((uint32_t)d) ^ xe);
                    uint32_t oB = ebase + (pb((uint32_t)d + 2) ^ xe);
                    __half2 h01 = *(__half2*)(sm + SO_EH + oA);
                    __half2 h23 = *(__half2*)(sm + SO_EH + oB);
                    __half2 l01 = *(__half2*)(sm + SO_EL + oA);
                    __half2 l23 = *(__half2*)(sm + SO_EL + oB);
                    float q0 = __half2float(h01.x) + __half2float(l01.x);
                    float q1 = __half2float(h01.y) + __half2float(l01.y);
                    float q2 = __half2float(h23.x) + __half2float(l23.x);
                    float q3 = __half2float(h23.y) + __half2float(l23.y);
                    *reinterpret_cast<float4*>(oq + d) = make_float4(q0, q1, q2, q3);
                }
            } else if (half == 0) {
                if (d3 - d1 >= MARGIN) {
                    int p = atomicAdd(s_qn, 1);
                    s_que[p] = rloc;
                } else {
                    int p = atomicAdd(s_qn2, 1);
                    s_que2[p] = rloc;
                }
            }
        }
        __syncthreads();

        // ---- Phase B: 2-candidate exact duel, one row per WARP ----
        {
            const int qn = *s_qn;
            for (int j = wid; j < qn; j += 16) {
                const int rloc = s_que[j];
                const int row  = tile * TILE_M + rloc;
                uint4 K = s_top[rloc];
                int i1 = (int)(K.x & 511u), i2 = (int)(K.y & 511u);
                const float* xr = x + (size_t)row * DDIM;
                float2 xv = __ldg((const float2*)(xr + 2 * lane));
                uint32_t pbo = pb((uint32_t)(2 * lane));
                float p1, p2;
                {
                    uint32_t o1 = (uint32_t)i1 * 128u + (pbo ^ (((uint32_t)i1 & 7u) * 16u));
                    uint32_t o2 = (uint32_t)i2 * 128u + (pbo ^ (((uint32_t)i2 & 7u) * 16u));
                    __half2 h1v = *(__half2*)(sm + SO_EH + o1);
                    __half2 l1v = *(__half2*)(sm + SO_EL + o1);
                    __half2 h2v = *(__half2*)(sm + SO_EH + o2);
                    __half2 l2v = *(__half2*)(sm + SO_EL + o2);
                    float a0 = xv.x - (__half2float(h1v.x) + __half2float(l1v.x));
                    float a1 = xv.y - (__half2float(h1v.y) + __half2float(l1v.y));
                    p1 = fmaf(a0, a0, a1 * a1);
                    float b0 = xv.x - (__half2float(h2v.x) + __half2float(l2v.x));
                    float b1 = xv.y - (__half2float(h2v.y) + __half2float(l2v.y));
                    p2 = fmaf(b0, b0, b1 * b1);
                }
#pragma unroll
                for (int o = 16; o > 0; o >>= 1) {
                    p1 += __shfl_xor_sync(0xffffffffu, p1, o);
                    p2 += __shfl_xor_sync(0xffffffffu, p2, o);
                }
                int bidx = i1; float be = p1;
                if (p2 < be || (p2 == be && i2 < bidx)) { be = p2; bidx = i2; }
                uint32_t oe = (uint32_t)bidx * 128u + (pbo ^ (((uint32_t)bidx & 7u) * 16u));
                __half2 hv = *(__half2*)(sm + SO_EH + oe);
                __half2 lv = *(__half2*)(sm + SO_EL + oe);
                float q0 = __half2float(hv.x) + __half2float(lv.x);
                float q1 = __half2float(hv.y) + __half2float(lv.y);
                *(float2*)(out_q + (size_t)row * DDIM + 2 * lane) = make_float2(q0, q1);
                if (lane == 0) {
                    out_idx[row] = (float)bidx;
                    atomicAdd(&s_hist[bidx], 1);
                    loss_acc += be;
                }
            }
        }
        __syncthreads();

        // ---- Phase C: rare full exact rescan, one row per block ----
        {
            const int qn2 = *s_qn2;
            for (int qi = 0; qi < qn2; qi++) {
                if (tid == 0) *s_b64 = 0xFFFFFFFFFFFFFFFFull;
                __syncthreads();
                const int rloc = s_que2[qi];
                const int row  = tile * TILE_M + rloc;
                const float* xr = x + (size_t)row * DDIM;
                float a0 = 0.f, a1 = 0.f;
                uint32_t ebase = (uint32_t)tid * 128u;
                uint32_t xe = ((uint32_t)tid & 7u) * 16u;
#pragma unroll 8
                for (int p = 0; p < 32; p++) {
                    uint32_t off = ebase + (((((uint32_t)p & 3u) * 32u) + (((uint32_t)p >> 3) * 8u)
                                            + ((((uint32_t)p >> 2) & 1u) * 4u)) ^ xe);
                    __half2 h2v = *(const __half2*)(sm + SO_EH + off);
                    __half2 l2v = *(const __half2*)(sm + SO_EL + off);
                    float2 xv = __ldg((const float2*)(xr + 2 * p));
                    float t0 = xv.x - (__half2float(h2v.x) + __half2float(l2v.x));
                    float t1 = xv.y - (__half2float(h2v.y) + __half2float(l2v.y));
                    a0 = fmaf(t0, t0, a0);
                    a1 = fmaf(t1, t1, a1);
                }
                float dv = a0 + a1;
                unsigned long long loc =
                    (((unsigned long long)__float_as_uint(dv)) << 32) | (unsigned)tid;
#pragma unroll
                for (int o = 16; o > 0; o >>= 1) {
                    unsigned long long ov = __shfl_xor_sync(0xffffffffu, loc, o);
                    loc = min(loc, ov);
                }
                if (lane == 0) atomicMin(s_b64, loc);
                __syncthreads();
                const unsigned long long win = *s_b64;
                const int bidx = (int)(win & 511u);
                if (tid < 32) {
                    int d = tid * 2;
                    uint32_t eb2 = (uint32_t)bidx * 128u;
                    uint32_t xe2 = ((uint32_t)bidx & 7u) * 16u;
                    uint32_t off = eb2 + (pb((uint32_t)d) ^ xe2);
                    __half2 h2v = *(__half2*)(sm + SO_EH + off);
                    __half2 l2v = *(__half2*)(sm + SO_EL + off);
                    float q0 = __half2float(h2v.x) + __half2float(l2v.x);
                    float q1 = __half2float(h2v.y) + __half2float(l2v.y);
                    *(float2*)(out_q + (size_t)row * DDIM + d) = make_float2(q0, q1);
                }
                if (tid == 0) {
                    out_idx[row] = (float)bidx;
                    atomicAdd(&s_hist[bidx], 1);
                    loss_acc += __uint_as_float((uint32_t)(win >> 32));
                }
                __syncthreads();
            }
        }
        __syncthreads();
        buf ^= 1;
    }

#pragma unroll
    for (int o = 16; o > 0; o >>= 1)
        loss_acc += __shfl_xor_sync(0xffffffffu, loss_acc, o);
    if (lane == 0) atomicAdd(&g_loss, loss_acc);

    {
        int c = s_hist[tid];
        if (c) atomicAdd(&g_cluster[tid], (float)c);
    }
}

// ---------------------------------------------------------------------------
__global__ __launch_bounds__(512)
void k_dw(const float* __restrict__ x, const float* __restrict__ idxf) {
    extern __shared__ float sdw[];          // [64][513]
    const int t = threadIdx.x;
    const int d = t & 63;
    const int rs = t >> 6;
    const int base = blockIdx.x * 1024;
    for (int i = t; i < 64 * 513; i += 512) sdw[i] = 0.f;
    __syncthreads();
#pragma unroll 1
    for (int j0 = 0; j0 < 1024; j0 += 32) {
        float xv[4]; int cd[4];
#pragma unroll
        for (int u = 0; u < 4; u++) {
            int r = base + j0 + rs * 4 + u;
            cd[u] = (int)__ldg(&idxf[r]);
            xv[u] = __ldg(&x[(size_t)r * 64 + d]);
        }
        float s = xv[0]; int c = cd[0];
#pragma unroll
        for (int u = 1; u < 4; u++) {
            if (cd[u] == c) s += xv[u];
            else { atomicAdd(&sdw[d * 513 + c], s); c = cd[u]; s = xv[u]; }
        }
        atomicAdd(&sdw[d * 513 + c], s);
    }
    __syncthreads();
    for (int i = t; i < 64 * 512; i += 512) {
        int dd = i >> 9, k = i & 511;
        float v = sdw[dd * 513 + k];
        if (v != 0.f) atomicAdd(&g_dw[i], v);
    }
}

// ---------------------------------------------------------------------------
__global__ void k_final(const float* __restrict__ ehc,
                        const float* __restrict__ ehd,
                        const int* __restrict__ counter,
                        float* __restrict__ out) {
    __shared__ float red_n[512];
    __shared__ float red_p[512];

    const int k = threadIdx.x;
    const int d = blockIdx.x;
    const float one_minus_decay = 0.01f;

    float cn = g_cluster[k];
    float t = (float)(*counter + 1);
    float debias = 1.0f - powf(0.99f, t);
    float inv_debias = 1.0f / debias;

    float h    = ehc[k];
    float nhc  = h - (h - cn) * one_minus_decay;
    float avgc = nhc * inv_debias;

    red_n[k] = avgc;
    float p = cn * (1.0f / (float)NROWS);
    red_p[k] = (d == 0) ? p * logf(p + 1e-10f) : 0.f;
    __syncthreads();
#pragma unroll
    for (int s = 256; s > 0; s >>= 1) {
        if (k < s) { red_n[k] += red_n[k + s]; red_p[k] += red_p[k + s]; }
        __syncthreads();
    }
    float n_total = red_n[0];
    float smoothed = (avgc + 1e-5f) / (n_total + (float)KCB * 1e-5f) * n_total;

    float dw  = g_dw[d * KCB + k];
    float hd  = ehd[d * KCB + k];
    float nhd = hd - (hd - dw) * one_minus_decay;
    out[OFF_EMB + d * KCB + k] = (nhd * inv_debias) / smoothed;

    if (d == 0 && k == 0) {
        out[OFF_LOSS] = 0.25f * g_loss / (float)((size_t)NROWS * DDIM);
        out[OFF_PERP] = expf(-red_p[0]);
    }
}

// ---------------------------------------------------------------------------
extern "C" void kernel_launch(void* const* d_in, const int* in_sizes, int n_in,
                              void* d_out, int out_size) {
    const float* x       = (const float*)d_in[0];
    const float* emb     = (const float*)d_in[1];
    const float* ehc     = (const float*)d_in[2];
    const float* ehd     = (const float*)d_in[3];
    const int*   counter = (const int*)d_in[4];
    float* out = (float*)d_out;

    cudaFuncSetAttribute(k_main, cudaFuncAttributeMaxDynamicSharedMemorySize,
                         (int)SMEM_SZ);
    cudaFuncSetAttribute(k_dw, cudaFuncAttributeMaxDynamicSharedMemorySize,
                         64 * 513 * 4);

    k_prep<<<8, 512>>>(emb);
    k_conv<<<1024, 512>>>(x);
    k_zero<<<64, 512>>>();
    k_main<<<GRID_MAIN, THREADS, SMEM_SZ>>>(x, emb, out + OFF_Q, out + OFF_IDX);
    k_dw<<<128, 512, 64 * 513 * 4>>>(x, out + OFF_IDX);
    k_final<<<64, 512>>>(ehc, ehd, counter, out);
}

// round 12
// speedup vs baseline: 1.0825x; 1.0825x over previous
#include <cuda_runtime.h>
#include <cuda_fp16.h>
#include <cstdint>
#include <math.h>

#define NROWS 131072
#define DDIM  64
#define KCB   512
#define TILE_M 128
#define NTILES (NROWS / TILE_M)     // 1024 -> 6.92 tiles/CTA, 98.8% balanced
#define GRID_MAIN 148
#define THREADS 256

#define OFF_Q    0
#define OFF_LOSS (NROWS * DDIM)
#define OFF_PERP (OFF_LOSS + 1)
#define OFF_EMB  (OFF_PERP + 1)
#define OFF_IDX  (OFF_EMB + DDIM * KCB)

#define MARGIN 0.15625f
#define MASKH  0xFFFFFE00u
#define KEYBIAS 256.0f
#define SENT 0x7F7FFFFFu

__device__ float g_dw[DDIM * KCB];
__device__ float g_cluster[KCB];
__device__ float g_loss;
__device__ float g_enorm[KCB];

__device__ __forceinline__ uint32_t pb(uint32_t d) {
    return ((d >> 1) & 3u) * 32u + (d >> 4) * 8u + ((d >> 3) & 1u) * 4u + (d & 1u) * 2u;
}

// smem layout (bytes)
#define SO_EH    0u          // 65536
#define SO_EL    65536u      // 65536
#define SO_XH    131072u     // 16384 (128 rows fp16 packed)
#define SO_EN2   147456u     // 2048
#define SO_XN    149504u     // 512
#define SO_TOP   150016u     // 2048
#define SO_HIST  152064u     // 2048
#define SO_QUE   154112u     // 512
#define SO_QUE2  154624u     // 512
#define SO_QN    155136u     // 4
#define SO_QN2   155140u     // 4
#define SO_B64   155144u     // 8
#define SMEM_SZ  155152u

__device__ __forceinline__ void mma_f16(float* d, uint32_t a0, uint32_t a1,
                                        uint32_t a2, uint32_t a3,
                                        uint32_t b0, uint32_t b1) {
    asm volatile(
        "mma.sync.aligned.m16n8k16.row.col.f32.f16.f16.f32 "
        "{%0,%1,%2,%3}, {%4,%5,%6,%7}, {%8,%9}, {%0,%1,%2,%3};\n"
        : "+f"(d[0]), "+f"(d[1]), "+f"(d[2]), "+f"(d[3])
        : "r"(a0), "r"(a1), "r"(a2), "r"(a3), "r"(b0), "r"(b1));
}

__device__ __forceinline__ void ins3(uint32_t& m1, uint32_t& m2, uint32_t& m3,
                                     uint32_t k) {
    uint32_t h1 = max(m1, k); m1 = min(m1, k);
    uint32_t h2 = max(m2, h1); m2 = min(m2, h1);
    m3 = min(m3, h2);
}
__device__ __forceinline__ uint32_t mkkey(float dist, uint32_t n) {
    uint32_t r;
    asm("bfi.b32 %0, %1, %2, 0, 9;" : "=r"(r) : "r"(n), "r"(__float_as_uint(dist)));
    return r;
}

__device__ __forceinline__ void do_kb(
    const char* sm, int kb, int g, int q,
    const uint4& A0a, const uint4& A0b, const uint4& A1a, const uint4& A1b,
    const float* s_en2, uint32_t c0, uint32_t c1,
    uint32_t& m11, uint32_t& m12, uint32_t& m13,
    uint32_t& m21, uint32_t& m22, uint32_t& m23)
{
    float acc[8][4];
#pragma unroll
    for (int nt = 0; nt < 8; nt++)
#pragma unroll
        for (int j = 0; j < 4; j++) acc[nt][j] = 0.f;

#pragma unroll
    for (int nt = 0; nt < 8; nt++) {
        uint32_t rowb = (uint32_t)(kb * 64 + nt * 8 + g) * 128u;
        uint4 B0 = *(const uint4*)(sm + SO_EH + rowb + c0);
        uint4 B1 = *(const uint4*)(sm + SO_EH + rowb + c1);
        mma_f16(acc[nt], A0a.x, A1a.x, A0a.y, A1a.y, B0.x, B0.y);
        mma_f16(acc[nt], A0a.z, A1a.z, A0a.w, A1a.w, B0.z, B0.w);
        mma_f16(acc[nt], A0b.x, A1b.x, A0b.y, A1b.y, B1.x, B1.y);
        mma_f16(acc[nt], A0b.z, A1b.z, A0b.w, A1b.w, B1.z, B1.w);
    }
#pragma unroll
    for (int nt = 0; nt < 8; nt++) {
        uint32_t n0 = (uint32_t)(kb * 64 + nt * 8 + q * 2);
        float2 en = *(const float2*)&s_en2[n0];
        uint32_t k0 = mkkey(fmaf(-2.f, acc[nt][0], en.x), n0);
        uint32_t k1 = mkkey(fmaf(-2.f, acc[nt][1], en.y), n0 + 1);
        uint32_t k2 = mkkey(fmaf(-2.f, acc[nt][2], en.x), n0);
        uint32_t k3 = mkkey(fmaf(-2.f, acc[nt][3], en.y), n0 + 1);
        ins3(m11, m12, m13, k0);
        ins3(m11, m12, m13, k1);
        ins3(m21, m22, m23, k2);
        ins3(m21, m22, m23, k3);
    }
}

// ---------------------------------------------------------------------------
__global__ void k_prep(const float* __restrict__ emb) {
    __shared__ float red[8][64];
    const int t = threadIdx.x, b = blockIdx.x;
    const int kk = t & 63, part = t >> 6;
    const int k = b * 64 + kk;
    float s = 0.f;
#pragma unroll
    for (int j = 0; j < 8; j++) {
        float e = emb[(part * 8 + j) * KCB + k];
        s = fmaf(e, e, s);
    }
    red[part][kk] = s;
    __syncthreads();
    if (t < 64) {
        float tot = red[0][t];
#pragma unroll
        for (int p = 1; p < 8; p++) tot += red[p][t];
        g_enorm[b * 64 + t] = tot;
    }
    if (b == 0) {
        g_cluster[t] = 0.f;
        if (t == 0) g_loss = 0.f;
    }
}
__global__ void k_zero_a() { g_dw[blockIdx.x * 512 + threadIdx.x] = 0.f; }
__global__ void k_zero_b() { g_dw[16384 + blockIdx.x * 512 + threadIdx.x] = 0.f; }

// ---------------------------------------------------------------------------
__global__ __launch_bounds__(THREADS, 1)
void k_main(const float* __restrict__ x, const float* __restrict__ emb,
            float* __restrict__ out_q, float* __restrict__ out_idx) {
    extern __shared__ __align__(1024) char sm[];
    const int tid  = threadIdx.x;
    const int wid  = tid >> 5;
    const int lane = tid & 31;
    const int g    = lane >> 2;
    const int q    = lane & 3;

    float* s_en2  = (float*)(sm + SO_EN2);
    float* s_xn   = (float*)(sm + SO_XN);
    uint4* s_top  = (uint4*)(sm + SO_TOP);
    int*   s_hist = (int*)(sm + SO_HIST);
    int*   s_que  = (int*)(sm + SO_QUE);
    int*   s_que2 = (int*)(sm + SO_QUE2);
    int*   s_qn   = (int*)(sm + SO_QN);
    int*   s_qn2  = (int*)(sm + SO_QN2);
    unsigned long long* s_b64 = (unsigned long long*)(sm + SO_B64);

    for (int i = tid; i < DDIM * KCB; i += THREADS) {
        uint32_t d = (uint32_t)i >> 9, k = (uint32_t)i & 511u;
        float e = emb[i];
        __half h = __float2half_rn(e);
        __half l = __float2half_rn(e - __half2float(h));
        uint32_t off = k * 128u + (pb(d) ^ ((k & 7u) * 16u));
        *(__half*)(sm + SO_EH + off) = h;
        *(__half*)(sm + SO_EL + off) = l;
    }
    for (int i = tid; i < KCB; i += THREADS) {
        s_en2[i] = g_enorm[i] + KEYBIAS;
        s_hist[i] = 0;
    }
    __syncthreads();

    const int r0 = wid * 16 + g;    // wid 0..7 -> rows 0..127
    const int r1 = r0 + 8;
    const uint32_t c0 = ((uint32_t)q * 32u) ^ ((uint32_t)g * 16u);
    const uint32_t c1 = ((uint32_t)q * 32u + 16u) ^ ((uint32_t)g * 16u);

    float loss_acc = 0.f;

    for (int tile = blockIdx.x; tile < NTILES; tile += gridDim.x) {
        const float* xt = x + (size_t)tile * TILE_M * DDIM;

        if (tid == 0) { *s_qn = 0; *s_qn2 = 0; }
        // ---- Stage x tile (fp16 packed) + per-row ||x||^2 ----
#pragma unroll
        for (int it = 0; it < 8; it++) {
            int i = it * THREADS + tid;
            float4 v = ((const float4*)xt)[i];
            uint32_t r = (uint32_t)i >> 4, c = ((uint32_t)i & 15u) * 4u;
            uint32_t xw = (r & 7u) * 16u;
            *(__half2*)(sm + SO_XH + r * 128u + (pb(c) ^ xw)) =
                __floats2half2_rn(v.x, v.y);
            *(__half2*)(sm + SO_XH + r * 128u + (pb(c + 2) ^ xw)) =
                __floats2half2_rn(v.z, v.w);
            float pn = fmaf(v.x, v.x, fmaf(v.y, v.y, fmaf(v.z, v.z, v.w * v.w)));
            pn += __shfl_xor_sync(0xffffffffu, pn, 1);
            pn += __shfl_xor_sync(0xffffffffu, pn, 2);
            pn += __shfl_xor_sync(0xffffffffu, pn, 4);
            pn += __shfl_xor_sync(0xffffffffu, pn, 8);
            if ((tid & 15) == 0) s_xn[r] = pn;
        }
        __syncthreads();

        uint4 A0a = *(const uint4*)(sm + SO_XH + (uint32_t)r0 * 128u + c0);
        uint4 A0b = *(const uint4*)(sm + SO_XH + (uint32_t)r0 * 128u + c1);
        uint4 A1a = *(const uint4*)(sm + SO_XH + (uint32_t)r1 * 128u + c0);
        uint4 A1b = *(const uint4*)(sm + SO_XH + (uint32_t)r1 * 128u + c1);

        uint32_t e11 = SENT, e12 = SENT, e13 = SENT;
        uint32_t o11 = SENT, o12 = SENT, o13 = SENT;
        uint32_t e21 = SENT, e22 = SENT, e23 = SENT;
        uint32_t o21 = SENT, o22 = SENT, o23 = SENT;

#pragma unroll 1
        for (int kbp = 0; kbp < 4; kbp++) {
            do_kb(sm, 2 * kbp,     g, q, A0a, A0b, A1a, A1b, s_en2, c0, c1,
                  e11, e12, e13, e21, e22, e23);
            do_kb(sm, 2 * kbp + 1, g, q, A0a, A0b, A1a, A1b, s_en2, c0, c1,
                  o11, o12, o13, o21, o22, o23);
        }
        ins3(e11, e12, e13, o11); ins3(e11, e12, e13, o12); ins3(e11, e12, e13, o13);
        ins3(e21, e22, e23, o21); ins3(e21, e22, e23, o22); ins3(e21, e22, e23, o23);

#pragma unroll
        for (int o = 1; o <= 2; o <<= 1) {
            uint32_t q1 = __shfl_xor_sync(0xffffffffu, e11, o);
            uint32_t q2 = __shfl_xor_sync(0xffffffffu, e12, o);
            uint32_t q3 = __shfl_xor_sync(0xffffffffu, e13, o);
            ins3(e11, e12, e13, q1);
            ins3(e11, e12, e13, q2);
            ins3(e11, e12, e13, q3);
            q1 = __shfl_xor_sync(0xffffffffu, e21, o);
            q2 = __shfl_xor_sync(0xffffffffu, e22, o);
            q3 = __shfl_xor_sync(0xffffffffu, e23, o);
            ins3(e21, e22, e23, q1);
            ins3(e21, e22, e23, q2);
            ins3(e21, e22, e23, q3);
        }
        if (q == 0) {
            s_top[r0] = make_uint4(e11, e12, e13, 0u);
            s_top[r1] = make_uint4(e21, e22, e23, 0u);
        }
        __syncthreads();

        // ---- Phase A: uniform direct emission; queue hard rows ----
        {
            const int rloc = tid >> 1;           // 0..127
            const int half = tid & 1;
            const int row  = tile * TILE_M + rloc;
            uint4 K = s_top[rloc];
            float d1 = __uint_as_float(K.x & MASKH);
            float d2 = __uint_as_float(K.y & MASKH);
            float d3 = __uint_as_float(K.z & MASKH);
            int bidx = (int)(K.x & 511u);
            if (d2 - d1 >= MARGIN) {
                if (half == 0) {
                    out_idx[row] = (float)bidx;
                    atomicAdd(&s_hist[bidx], 1);
                    loss_acc += d1 - KEYBIAS + s_xn[rloc]
                              + __uint_as_float(K.x & 0xFF800000u) * 3.0517578125e-05f;
                }
                float* oq = out_q + (size_t)row * DDIM;
                uint32_t ebase = (uint32_t)bidx * 128u;
                uint32_t xe = ((uint32_t)bidx & 7u) * 16u;
#pragma unroll
                for (int d = half * 32; d < half * 32 + 32; d += 4) {
                    uint32_t oA = ebase + (pb((uint32_t)d) ^ xe);
                    uint32_t oB = ebase + (pb((uint32_t)d + 2) ^ xe);
                    __half2 h01 = *(__half2*)(sm + SO_EH + oA);
                    __half2 h23 = *(__half2*)(sm + SO_EH + oB);
                    __half2 l01 = *(__half2*)(sm + SO_EL + oA);
                    __half2 l23 = *(__half2*)(sm + SO_EL + oB);
                    float q0 = __half2float(h01.x) + __half2float(l01.x);
                    float q1 = __half2float(h01.y) + __half2float(l01.y);
                    float q2 = __half2float(h23.x) + __half2float(l23.x);
                    float q3 = __half2float(h23.y) + __half2float(l23.y);
                    *reinterpret_cast<float4*>(oq + d) = make_float4(q0, q1, q2, q3);
                }
            } else if (half == 0) {
                if (d3 - d1 >= MARGIN) {
                    int p = atomicAdd(s_qn, 1);
                    s_que[p] = rloc;
                } else {
                    int p = atomicAdd(s_qn2, 1);
                    s_que2[p] = rloc;
                }
            }
        }
        __syncthreads();

        // ---- Phase B: 2-candidate exact duel, one row per WARP ----
        {
            const int qn = *s_qn;
            for (int j = wid; j < qn; j += 8) {
                const int rloc = s_que[j];
                const int row  = tile * TILE_M + rloc;
                uint4 K = s_top[rloc];
                int i1 = (int)(K.x & 511u), i2 = (int)(K.y & 511u);
                const float* xr = x + (size_t)row * DDIM;
                float2 xv = __ldg((const float2*)(xr + 2 * lane));
                uint32_t pbo = pb((uint32_t)(2 * lane));
                float p1, p2;
                {
                    uint32_t o1 = (uint32_t)i1 * 128u + (pbo ^ (((uint32_t)i1 & 7u) * 16u));
                    uint32_t o2 = (uint32_t)i2 * 128u + (pbo ^ (((uint32_t)i2 & 7u) * 16u));
                    __half2 h1v = *(__half2*)(sm + SO_EH + o1);
                    __half2 l1v = *(__half2*)(sm + SO_EL + o1);
                    __half2 h2v = *(__half2*)(sm + SO_EH + o2);
                    __half2 l2v = *(__half2*)(sm + SO_EL + o2);
                    float a0 = xv.x - (__half2float(h1v.x) + __half2float(l1v.x));
                    float a1 = xv.y - (__half2float(h1v.y) + __half2float(l1v.y));
                    p1 = fmaf(a0, a0, a1 * a1);
                    float b0 = xv.x - (__half2float(h2v.x) + __half2float(l2v.x));
                    float b1 = xv.y - (__half2float(h2v.y) + __half2float(l2v.y));
                    p2 = fmaf(b0, b0, b1 * b1);
                }
#pragma unroll
                for (int o = 16; o > 0; o >>= 1) {
                    p1 += __shfl_xor_sync(0xffffffffu, p1, o);
                    p2 += __shfl_xor_sync(0xffffffffu, p2, o);
                }
                int bidx = i1; float be = p1;
                if (p2 < be || (p2 == be && i2 < bidx)) { be = p2; bidx = i2; }
                uint32_t oe = (uint32_t)bidx * 128u + (pbo ^ (((uint32_t)bidx & 7u) * 16u));
                __half2 hv = *(__half2*)(sm + SO_EH + oe);
                __half2 lv = *(__half2*)(sm + SO_EL + oe);
                float q0 = __half2float(hv.x) + __half2float(lv.x);
                float q1 = __half2float(hv.y) + __half2float(lv.y);
                *(float2*)(out_q + (size_t)row * DDIM + 2 * lane) = make_float2(q0, q1);
                if (lane == 0) {
                    out_idx[row] = (float)bidx;
                    atomicAdd(&s_hist[bidx], 1);
                    loss_acc += be;
                }
            }
        }
        __syncthreads();

        // ---- Phase C: rare full exact rescan, one row per block ----
        {
            const int qn2 = *s_qn2;
            for (int qi = 0; qi < qn2; qi++) {
                if (tid == 0) *s_b64 = 0xFFFFFFFFFFFFFFFFull;
                __syncthreads();
                const int rloc = s_que2[qi];
                const int row  = tile * TILE_M + rloc;
                const float* xr = x + (size_t)row * DDIM;
                unsigned long long loc = 0xFFFFFFFFFFFFFFFFull;
#pragma unroll
                for (int cc = 0; cc < 2; cc++) {
                    const int code = tid + cc * 256;
                    float a0 = 0.f, a1 = 0.f;
                    uint32_t ebase = (uint32_t)code * 128u;
                    uint32_t xe = ((uint32_t)code & 7u) * 16u;
#pragma unroll 8
                    for (int p = 0; p < 32; p++) {
                        uint32_t off = ebase + (((((uint32_t)p & 3u) * 32u) + (((uint32_t)p >> 3) * 8u)
                                                + ((((uint32_t)p >> 2) & 1u) * 4u)) ^ xe);
                        __half2 h2v = *(const __half2*)(sm + SO_EH + off);
                        __half2 l2v = *(const __half2*)(sm + SO_EL + off);
                        float2 xv = __ldg((const float2*)(xr + 2 * p));
                        float t0 = xv.x - (__half2float(h2v.x) + __half2float(l2v.x));
                        float t1 = xv.y - (__half2float(h2v.y) + __half2float(l2v.y));
                        a0 = fmaf(t0, t0, a0);
                        a1 = fmaf(t1, t1, a1);
                    }
                    float dv = a0 + a1;
                    unsigned long long kk =
                        (((unsigned long long)__float_as_uint(dv)) << 32) | (unsigned)code;
                    loc = min(loc, kk);
                }
#pragma unroll
                for (int o = 16; o > 0; o >>= 1) {
                    unsigned long long ov = __shfl_xor_sync(0xffffffffu, loc, o);
                    loc = min(loc, ov);
                }
                if (lane == 0) atomicMin(s_b64, loc);
                __syncthreads();
                const unsigned long long win = *s_b64;
                const int bidx = (int)(win & 511u);
                if (tid < 32) {
                    int d = tid * 2;
                    uint32_t eb2 = (uint32_t)bidx * 128u;
                    uint32_t xe2 = ((uint32_t)bidx & 7u) * 16u;
                    uint32_t off = eb2 + (pb((uint32_t)d) ^ xe2);
                    __half2 h2v = *(__half2*)(sm + SO_EH + off);
                    __half2 l2v = *(__half2*)(sm + SO_EL + off);
                    float q0 = __half2float(h2v.x) + __half2float(l2v.x);
                    float q1 = __half2float(h2v.y) + __half2float(l2v.y);
                    *(float2*)(out_q + (size_t)row * DDIM + d) = make_float2(q0, q1);
                }
                if (tid == 0) {
                    out_idx[row] = (float)bidx;
                    atomicAdd(&s_hist[bidx], 1);
                    loss_acc += __uint_as_float((uint32_t)(win >> 32));
                }
                __syncthreads();
            }
        }
        __syncthreads();
    }

#pragma unroll
    for (int o = 16; o > 0; o >>= 1)
        loss_acc += __shfl_xor_sync(0xffffffffu, loss_acc, o);
    if (lane == 0) atomicAdd(&g_loss, loss_acc);

    for (int i = tid; i < KCB; i += THREADS) {
        int c = s_hist[i];
        if (c) atomicAdd(&g_cluster[i], (float)c);
    }
}

// ---------------------------------------------------------------------------
__global__ __launch_bounds__(512)
void k_dw(const float* __restrict__ x, const float* __restrict__ idxf) {
    extern __shared__ float sdw[];          // [64][513]
    const int t = threadIdx.x;
    const int d = t & 63;
    const int rs = t >> 6;
    const int base = blockIdx.x * 1024;
    for (int i = t; i < 64 * 513; i += 512) sdw[i] = 0.f;
    __syncthreads();
#pragma unroll 1
    for (int j0 = 0; j0 < 1024; j0 += 32) {
        float xv[4]; int cd[4];
#pragma unroll
        for (int u = 0; u < 4; u++) {
            int r = base + j0 + rs * 4 + u;
            cd[u] = (int)__ldg(&idxf[r]);
            xv[u] = __ldg(&x[(size_t)r * 64 + d]);
        }
        float s = xv[0]; int c = cd[0];
#pragma unroll
        for (int u = 1; u < 4; u++) {
            if (cd[u] == c) s += xv[u];
            else { atomicAdd(&sdw[d * 513 + c], s); c = cd[u]; s = xv[u]; }
        }
        atomicAdd(&sdw[d * 513 + c], s);
    }
    __syncthreads();
    for (int i = t; i < 64 * 512; i += 512) {
        int dd = i >> 9, k = i & 511;
        float v = sdw[dd * 513 + k];
        if (v != 0.f) atomicAdd(&g_dw[i], v);
    }
}

// ---------------------------------------------------------------------------
__global__ void k_final(const float* __restrict__ ehc,
                        const float* __restrict__ ehd,
                        const int* __restrict__ counter,
                        float* __restrict__ out) {
    __shared__ float red_n[512];
    __shared__ float red_p[512];

    const int k = threadIdx.x;
    const int d = blockIdx.x;
    const float one_minus_decay = 0.01f;

    float cn = g_cluster[k];
    float t = (float)(*counter + 1);
    float debias = 1.0f - powf(0.99f, t);
    float inv_debias = 1.0f / debias;

    float h    = ehc[k];
    float nhc  = h - (h - cn) * one_minus_decay;
    float avgc = nhc * inv_debias;

    red_n[k] = avgc;
    float p = cn * (1.0f / (float)NROWS);
    red_p[k] = (d == 0) ? p * logf(p + 1e-10f) : 0.f;
    __syncthreads();
#pragma unroll
    for (int s = 256; s > 0; s >>= 1) {
        if (k < s) { red_n[k] += red_n[k + s]; red_p[k] += red_p[k + s]; }
        __syncthreads();
    }
    float n_total = red_n[0];
    float smoothed = (avgc + 1e-5f) / (n_total + (float)KCB * 1e-5f) * n_total;

    float dw  = g_dw[d * KCB + k];
    float hd  = ehd[d * KCB + k];
    float nhd = hd - (hd - dw) * one_minus_decay;
    out[OFF_EMB + d * KCB + k] = (nhd * inv_debias) / smoothed;

    if (d == 0 && k == 0) {
        out[OFF_LOSS] = 0.25f * g_loss / (float)((size_t)NROWS * DDIM);
        out[OFF_PERP] = expf(-red_p[0]);
    }
}

// ---------------------------------------------------------------------------
extern "C" void kernel_launch(void* const* d_in, const int* in_sizes, int n_in,
                              void* d_out, int out_size) {
    const float* x       = (const float*)d_in[0];
    const float* emb     = (const float*)d_in[1];
    const float* ehc     = (const float*)d_in[2];
    const float* ehd     = (const float*)d_in[3];
    const int*   counter = (const int*)d_in[4];
    float* out = (float*)d_out;

    cudaFuncSetAttribute(k_main, cudaFuncAttributeMaxDynamicSharedMemorySize,
                         (int)SMEM_SZ);
    cudaFuncSetAttribute(k_dw, cudaFuncAttributeMaxDynamicSharedMemorySize,
                         64 * 513 * 4);

    k_prep<<<8, 512>>>(emb);
    k_zero_a<<<32, 512>>>();
    k_zero_b<<<32, 512>>>();
    k_main<<<GRID_MAIN, THREADS, SMEM_SZ>>>(x, emb, out + OFF_Q, out + OFF_IDX);
    k_dw<<<128, 512, 64 * 513 * 4>>>(x, out + OFF_IDX);
    k_final<<<64, 512>>>(ehc, ehd, counter, out);
}

// round 13
// speedup vs baseline: 1.1032x; 1.0191x over previous
#include <cuda_runtime.h>
#include <cuda_fp16.h>
#include <cstdint>
#include <math.h>

#define NROWS 131072
#define DDIM  64
#define KCB   512
#define TILE_M 128
#define NTILES (NROWS / TILE_M)     // 1024 -> 6.92 tiles/CTA (98.8% balance)
#define GRID_MAIN 148
#define THREADS 512

#define OFF_Q    0
#define OFF_LOSS (NROWS * DDIM)
#define OFF_PERP (OFF_LOSS + 1)
#define OFF_EMB  (OFF_PERP + 1)
#define OFF_IDX  (OFF_EMB + DDIM * KCB)

#define MARGIN 0.15625f
#define MASKH  0xFFFFFE00u
#define KEYBIAS 256.0f
#define SENT 0x7F7FFFFFu

__device__ float g_dw[DDIM * KCB];
__device__ float g_cluster[KCB];
__device__ float g_loss;
__device__ float g_enorm[KCB];
__device__ uint2 g_que[NROWS];      // duel queue: {row, i1|(i2<<16)}
__device__ int   g_que2[NROWS];     // rescan queue: row
__device__ int   g_qn, g_qn2;

__device__ __forceinline__ uint32_t pb(uint32_t d) {
    return ((d >> 1) & 3u) * 32u + (d >> 4) * 8u + ((d >> 3) & 1u) * 4u + (d & 1u) * 2u;
}

// smem layout (bytes) for k_main
#define SO_EH    0u          // 65536
#define SO_EL    65536u      // 65536
#define SO_XH    131072u     // 16384 (128 rows fp16 packed)
#define SO_EN2   147456u     // 2048
#define SO_XN    149504u     // 512
#define SO_TOP   150016u     // 4096: [row][half] uint4
#define SO_HIST  154112u     // 2048
#define SMEM_SZ  156160u

__device__ __forceinline__ void mma_f16(float* d, uint32_t a0, uint32_t a1,
                                        uint32_t a2, uint32_t a3,
                                        uint32_t b0, uint32_t b1) {
    asm volatile(
        "mma.sync.aligned.m16n8k16.row.col.f32.f16.f16.f32 "
        "{%0,%1,%2,%3}, {%4,%5,%6,%7}, {%8,%9}, {%0,%1,%2,%3};\n"
        : "+f"(d[0]), "+f"(d[1]), "+f"(d[2]), "+f"(d[3])
        : "r"(a0), "r"(a1), "r"(a2), "r"(a3), "r"(b0), "r"(b1));
}

__device__ __forceinline__ void ins3(uint32_t& m1, uint32_t& m2, uint32_t& m3,
                                     uint32_t k) {
    uint32_t h1 = max(m1, k); m1 = min(m1, k);
    uint32_t h2 = max(m2, h1); m2 = min(m2, h1);
    m3 = min(m3, h2);
}
__device__ __forceinline__ uint32_t mkkey(float dist, uint32_t n) {
    uint32_t r;
    asm("bfi.b32 %0, %1, %2, 0, 9;" : "=r"(r) : "r"(n), "r"(__float_as_uint(dist)));
    return r;
}

__device__ __forceinline__ void do_kb(
    const char* sm, int kb, int g, int q,
    const uint4& A0a, const uint4& A0b, const uint4& A1a, const uint4& A1b,
    const float* s_en2, uint32_t c0, uint32_t c1,
    uint32_t& m11, uint32_t& m12, uint32_t& m13,
    uint32_t& m21, uint32_t& m22, uint32_t& m23)
{
    float acc[8][4];
#pragma unroll
    for (int nt = 0; nt < 8; nt++)
#pragma unroll
        for (int j = 0; j < 4; j++) acc[nt][j] = 0.f;

#pragma unroll
    for (int nt = 0; nt < 8; nt++) {
        uint32_t rowb = (uint32_t)(kb * 64 + nt * 8 + g) * 128u;
        uint4 B0 = *(const uint4*)(sm + SO_EH + rowb + c0);
        uint4 B1 = *(const uint4*)(sm + SO_EH + rowb + c1);
        mma_f16(acc[nt], A0a.x, A1a.x, A0a.y, A1a.y, B0.x, B0.y);
        mma_f16(acc[nt], A0a.z, A1a.z, A0a.w, A1a.w, B0.z, B0.w);
        mma_f16(acc[nt], A0b.x, A1b.x, A0b.y, A1b.y, B1.x, B1.y);
        mma_f16(acc[nt], A0b.z, A1b.z, A0b.w, A1b.w, B1.z, B1.w);
    }
#pragma unroll
    for (int nt = 0; nt < 8; nt++) {
        uint32_t n0 = (uint32_t)(kb * 64 + nt * 8 + q * 2);
        float2 en = *(const float2*)&s_en2[n0];
        uint32_t k0 = mkkey(fmaf(-2.f, acc[nt][0], en.x), n0);
        uint32_t k1 = mkkey(fmaf(-2.f, acc[nt][1], en.y), n0 + 1);
        uint32_t k2 = mkkey(fmaf(-2.f, acc[nt][2], en.x), n0);
        uint32_t k3 = mkkey(fmaf(-2.f, acc[nt][3], en.y), n0 + 1);
        ins3(m11, m12, m13, k0);
        ins3(m11, m12, m13, k1);
        ins3(m21, m22, m23, k2);
        ins3(m21, m22, m23, k3);
    }
}

// ---------------------------------------------------------------------------
__global__ void k_prep(const float* __restrict__ emb) {
    __shared__ float red[8][64];
    const int t = threadIdx.x, b = blockIdx.x;
    const int kk = t & 63, part = t >> 6;
    const int k = b * 64 + kk;
    float s = 0.f;
#pragma unroll
    for (int j = 0; j < 8; j++) {
        float e = emb[(part * 8 + j) * KCB + k];
        s = fmaf(e, e, s);
    }
    red[part][kk] = s;
    __syncthreads();
    if (t < 64) {
        float tot = red[0][t];
#pragma unroll
        for (int p = 1; p < 8; p++) tot += red[p][t];
        g_enorm[b * 64 + t] = tot;
    }
    if (b == 0) {
        g_cluster[t] = 0.f;
        if (t == 0) { g_loss = 0.f; g_qn = 0; g_qn2 = 0; }
    }
}
__global__ void k_zero_a() { g_dw[blockIdx.x * 512 + threadIdx.x] = 0.f; }
__global__ void k_zero_b() { g_dw[16384 + blockIdx.x * 512 + threadIdx.x] = 0.f; }

// ---------------------------------------------------------------------------
// Main: 512 threads; warps 0-7 scan codes 0-255, warps 8-15 scan 256-511.
// ---------------------------------------------------------------------------
__global__ __launch_bounds__(THREADS, 1)
void k_main(const float* __restrict__ x, const float* __restrict__ emb,
            float* __restrict__ out_q, float* __restrict__ out_idx) {
    extern __shared__ __align__(1024) char sm[];
    const int tid  = threadIdx.x;
    const int wid  = tid >> 5;
    const int lane = tid & 31;
    const int g    = lane >> 2;
    const int q    = lane & 3;
    const int half = wid >> 3;       // code half
    const int w8   = wid & 7;

    float* s_en2  = (float*)(sm + SO_EN2);
    float* s_xn   = (float*)(sm + SO_XN);
    uint4* s_top  = (uint4*)(sm + SO_TOP);
    int*   s_hist = (int*)(sm + SO_HIST);

    for (int i = tid; i < DDIM * KCB; i += THREADS) {
        uint32_t d = (uint32_t)i >> 9, k = (uint32_t)i & 511u;
        float e = emb[i];
        __half h = __float2half_rn(e);
        __half l = __float2half_rn(e - __half2float(h));
        uint32_t off = k * 128u + (pb(d) ^ ((k & 7u) * 16u));
        *(__half*)(sm + SO_EH + off) = h;
        *(__half*)(sm + SO_EL + off) = l;
    }
    s_en2[tid] = g_enorm[tid] + KEYBIAS;
    s_hist[tid] = 0;
    __syncthreads();

    const int r0 = w8 * 16 + g;      // rows 0..127 (both halves cover all rows)
    const int r1 = r0 + 8;
    const uint32_t c0 = ((uint32_t)q * 32u) ^ ((uint32_t)g * 16u);
    const uint32_t c1 = ((uint32_t)q * 32u + 16u) ^ ((uint32_t)g * 16u);

    float loss_acc = 0.f;

    for (int tile = blockIdx.x; tile < NTILES; tile += gridDim.x) {
        const float* xt = x + (size_t)tile * TILE_M * DDIM;

        // ---- Stage x tile (fp16 packed) + per-row ||x||^2 ----
#pragma unroll
        for (int it = 0; it < 4; it++) {
            int i = it * THREADS + tid;
            float4 v = ((const float4*)xt)[i];
            uint32_t r = (uint32_t)i >> 4, c = ((uint32_t)i & 15u) * 4u;
            uint32_t xw = (r & 7u) * 16u;
            *(__half2*)(sm + SO_XH + r * 128u + (pb(c) ^ xw)) =
                __floats2half2_rn(v.x, v.y);
            *(__half2*)(sm + SO_XH + r * 128u + (pb(c + 2) ^ xw)) =
                __floats2half2_rn(v.z, v.w);
            float pn = fmaf(v.x, v.x, fmaf(v.y, v.y, fmaf(v.z, v.z, v.w * v.w)));
            pn += __shfl_xor_sync(0xffffffffu, pn, 1);
            pn += __shfl_xor_sync(0xffffffffu, pn, 2);
            pn += __shfl_xor_sync(0xffffffffu, pn, 4);
            pn += __shfl_xor_sync(0xffffffffu, pn, 8);
            if ((tid & 15) == 0) s_xn[r] = pn;
        }
        __syncthreads();

        uint4 A0a = *(const uint4*)(sm + SO_XH + (uint32_t)r0 * 128u + c0);
        uint4 A0b = *(const uint4*)(sm + SO_XH + (uint32_t)r0 * 128u + c1);
        uint4 A1a = *(const uint4*)(sm + SO_XH + (uint32_t)r1 * 128u + c0);
        uint4 A1b = *(const uint4*)(sm + SO_XH + (uint32_t)r1 * 128u + c1);

        uint32_t e11 = SENT, e12 = SENT, e13 = SENT;
        uint32_t o11 = SENT, o12 = SENT, o13 = SENT;
        uint32_t e21 = SENT, e22 = SENT, e23 = SENT;
        uint32_t o21 = SENT, o22 = SENT, o23 = SENT;

        // this warp covers kb = half*4 .. half*4+3 (alternating chains)
#pragma unroll 1
        for (int kbp = 0; kbp < 2; kbp++) {
            do_kb(sm, half * 4 + 2 * kbp,     g, q, A0a, A0b, A1a, A1b,
                  s_en2, c0, c1, e11, e12, e13, e21, e22, e23);
            do_kb(sm, half * 4 + 2 * kbp + 1, g, q, A0a, A0b, A1a, A1b,
                  s_en2, c0, c1, o11, o12, o13, o21, o22, o23);
        }
        ins3(e11, e12, e13, o11); ins3(e11, e12, e13, o12); ins3(e11, e12, e13, o13);
        ins3(e21, e22, e23, o21); ins3(e21, e22, e23, o22); ins3(e21, e22, e23, o23);

#pragma unroll
        for (int o = 1; o <= 2; o <<= 1) {
            uint32_t q1 = __shfl_xor_sync(0xffffffffu, e11, o);
            uint32_t q2 = __shfl_xor_sync(0xffffffffu, e12, o);
            uint32_t q3 = __shfl_xor_sync(0xffffffffu, e13, o);
            ins3(e11, e12, e13, q1);
            ins3(e11, e12, e13, q2);
            ins3(e11, e12, e13, q3);
            q1 = __shfl_xor_sync(0xffffffffu, e21, o);
            q2 = __shfl_xor_sync(0xffffffffu, e22, o);
            q3 = __shfl_xor_sync(0xffffffffu, e23, o);
            ins3(e21, e22, e23, q1);
            ins3(e21, e22, e23, q2);
            ins3(e21, e22, e23, q3);
        }
        if (q == 0) {
            s_top[(r0 << 1) | half] = make_uint4(e11, e12, e13, 0u);
            s_top[(r1 << 1) | half] = make_uint4(e21, e22, e23, 0u);
        }
        __syncthreads();

        // ---- Phase A: merge halves, emit or queue (4 threads per row) ----
        {
            const int rloc = tid >> 2;
            const int q4   = tid & 3;
            const int row  = tile * TILE_M + rloc;
            uint4 Ka = s_top[rloc << 1];
            uint4 Kb = s_top[(rloc << 1) | 1];
            uint32_t m1 = Ka.x, m2 = Ka.y, m3 = Ka.z;
            ins3(m1, m2, m3, Kb.x);
            ins3(m1, m2, m3, Kb.y);
            ins3(m1, m2, m3, Kb.z);
            float d1 = __uint_as_float(m1 & MASKH);
            float d2 = __uint_as_float(m2 & MASKH);
            float d3 = __uint_as_float(m3 & MASKH);
            int bidx = (int)(m1 & 511u);
            if (d2 - d1 >= MARGIN) {
                if (q4 == 0) {
                    out_idx[row] = (float)bidx;
                    atomicAdd(&s_hist[bidx], 1);
                    loss_acc += d1 - KEYBIAS + s_xn[rloc]
                              + __uint_as_float(m1 & 0xFF800000u) * 3.0517578125e-05f;
                }
                float* oq = out_q + (size_t)row * DDIM;
                uint32_t ebase = (uint32_t)bidx * 128u;
                uint32_t xe = ((uint32_t)bidx & 7u) * 16u;
#pragma unroll
                for (int d = q4 * 16; d < q4 * 16 + 16; d += 4) {
                    uint32_t oA = ebase + (pb((uint32_t)d) ^ xe);
                    uint32_t oB = ebase + (pb((uint32_t)d + 2) ^ xe);
                    __half2 h01 = *(__half2*)(sm + SO_EH + oA);
                    __half2 h23 = *(__half2*)(sm + SO_EH + oB);
                    __half2 l01 = *(__half2*)(sm + SO_EL + oA);
                    __half2 l23 = *(__half2*)(sm + SO_EL + oB);
                    float q0 = __half2float(h01.x) + __half2float(l01.x);
                    float q1 = __half2float(h01.y) + __half2float(l01.y);
                    float q2 = __half2float(h23.x) + __half2float(l23.x);
                    float q3 = __half2float(h23.y) + __half2float(l23.y);
                    *reinterpret_cast<float4*>(oq + d) = make_float4(q0, q1, q2, q3);
                }
            } else if (q4 == 0) {
                if (d3 - d1 >= MARGIN) {
                    int p = atomicAdd(&g_qn, 1);
                    g_que[p] = make_uint2((unsigned)row,
                                          (m1 & 511u) | ((m2 & 511u) << 16));
                } else {
                    int p = atomicAdd(&g_qn2, 1);
                    g_que2[p] = row;
                }
            }
        }
        __syncthreads();
    }

#pragma unroll
    for (int o = 16; o > 0; o >>= 1)
        loss_acc += __shfl_xor_sync(0xffffffffu, loss_acc, o);
    if (lane == 0) atomicAdd(&g_loss, loss_acc);

    {
        int c = s_hist[tid];
        if (c) atomicAdd(&g_cluster[tid], (float)c);
    }
}

// ---------------------------------------------------------------------------
// Fix: exact fp32 resolution of queued rows. Stages fp32 codebook in smem.
//   duel rows: one warp per row (2 candidates); rescan rows: one block per row.
// ---------------------------------------------------------------------------
#define FX_E    0                        // floats: [64][513]
#define FX_XROW (64 * 513)               // 64 floats
#define FX_B64  (64 * 513 + 64)          // 2 floats (as ull)
#define FX_SZ   ((64 * 513 + 66) * 4)

__global__ __launch_bounds__(512)
void k_fix(const float* __restrict__ x, const float* __restrict__ emb,
           float* __restrict__ out_q, float* __restrict__ out_idx) {
    extern __shared__ float se[];
    const int tid = threadIdx.x;
    const int wid = tid >> 5;
    const int lane = tid & 31;
    float* xrow = se + FX_XROW;
    unsigned long long* b64 = (unsigned long long*)(se + FX_B64);

    for (int i = tid; i < 64 * 512; i += 512) {
        int d = i >> 9, k = i & 511;
        se[d * 513 + k] = emb[i];
    }
    __syncthreads();

    float loss_acc = 0.f;

    // ---- duels: warp per row ----
    const int qn = g_qn;
    for (int j = blockIdx.x * 16 + wid; j < qn; j += gridDim.x * 16) {
        uint2 e = g_que[j];
        const int row = (int)e.x;
        const int i1 = (int)(e.y & 511u), i2 = (int)((e.y >> 16) & 511u);
        float2 xv = __ldg((const float2*)(x + (size_t)row * DDIM + 2 * lane));
        float e10 = se[(2 * lane) * 513 + i1], e11v = se[(2 * lane + 1) * 513 + i1];
        float e20 = se[(2 * lane) * 513 + i2], e21v = se[(2 * lane + 1) * 513 + i2];
        float a0 = xv.x - e10, a1 = xv.y - e11v;
        float p1 = fmaf(a0, a0, a1 * a1);
        float b0 = xv.x - e20, b1 = xv.y - e21v;
        float p2 = fmaf(b0, b0, b1 * b1);
#pragma unroll
        for (int o = 16; o > 0; o >>= 1) {
            p1 += __shfl_xor_sync(0xffffffffu, p1, o);
            p2 += __shfl_xor_sync(0xffffffffu, p2, o);
        }
        int bidx = i1; float be = p1;
        float q0 = e10, q1 = e11v;
        if (p2 < be || (p2 == be && i2 < bidx)) { be = p2; bidx = i2; q0 = e20; q1 = e21v; }
        *(float2*)(out_q + (size_t)row * DDIM + 2 * lane) = make_float2(q0, q1);
        if (lane == 0) {
            out_idx[row] = (float)bidx;
            atomicAdd(&g_cluster[bidx], 1.f);
            loss_acc += be;
        }
    }

    // ---- rescans: block per row ----
    const int qn2 = g_qn2;
    for (int qi = blockIdx.x; qi < qn2; qi += gridDim.x) {
        const int row = g_que2[qi];
        if (tid < 32) {
            float2 v = ((const float2*)(x + (size_t)row * DDIM))[tid];
            xrow[2 * tid] = v.x;
            xrow[2 * tid + 1] = v.y;
        }
        if (tid == 0) *b64 = 0xFFFFFFFFFFFFFFFFull;
        __syncthreads();
        float a = 0.f;
#pragma unroll 8
        for (int d = 0; d < 64; d++) {
            float t = xrow[d] - se[d * 513 + tid];
            a = fmaf(t, t, a);
        }
        unsigned long long loc =
            (((unsigned long long)__float_as_uint(a)) << 32) | (unsigned)tid;
#pragma unroll
        for (int o = 16; o > 0; o >>= 1) {
            unsigned long long ov = __shfl_xor_sync(0xffffffffu, loc, o);
            loc = min(loc, ov);
        }
        if (lane == 0) atomicMin(b64, loc);
        __syncthreads();
        const unsigned long long win = *b64;
        const int bidx = (int)(win & 511u);
        if (tid < 64)
            out_q[(size_t)row * DDIM + tid] = se[tid * 513 + bidx];
        if (tid == 0) {
            out_idx[row] = (float)bidx;
            atomicAdd(&g_cluster[bidx], 1.f);
            loss_acc += __uint_as_float((uint32_t)(win >> 32));
        }
        __syncthreads();
    }

#pragma unroll
    for (int o = 16; o > 0; o >>= 1)
        loss_acc += __shfl_xor_sync(0xffffffffu, loss_acc, o);
    if (lane == 0 && loss_acc != 0.f) atomicAdd(&g_loss, loss_acc);
}

// ---------------------------------------------------------------------------
__global__ __launch_bounds__(512)
void k_dw(const float* __restrict__ x, const float* __restrict__ idxf) {
    extern __shared__ float sdw[];          // [64][513]
    const int t = threadIdx.x;
    const int d = t & 63;
    const int rs = t >> 6;
    const int base = blockIdx.x * 1024;
    for (int i = t; i < 64 * 513; i += 512) sdw[i] = 0.f;
    __syncthreads();
#pragma unroll 1
    for (int j0 = 0; j0 < 1024; j0 += 32) {
        float xv[4]; int cd[4];
#pragma unroll
        for (int u = 0; u < 4; u++) {
            int r = base + j0 + rs * 4 + u;
            cd[u] = (int)__ldg(&idxf[r]);
            xv[u] = __ldg(&x[(size_t)r * 64 + d]);
        }
        float s = xv[0]; int c = cd[0];
#pragma unroll
        for (int u = 1; u < 4; u++) {
            if (cd[u] == c) s += xv[u];
            else { atomicAdd(&sdw[d * 513 + c], s); c = cd[u]; s = xv[u]; }
        }
        atomicAdd(&sdw[d * 513 + c], s);
    }
    __syncthreads();
    for (int i = t; i < 64 * 512; i += 512) {
        int dd = i >> 9, k = i & 511;
        float v = sdw[dd * 513 + k];
        if (v != 0.f) atomicAdd(&g_dw[i], v);
    }
}

// ---------------------------------------------------------------------------
__global__ void k_final(const float* __restrict__ ehc,
                        const float* __restrict__ ehd,
                        const int* __restrict__ counter,
                        float* __restrict__ out) {
    __shared__ float red_n[512];
    __shared__ float red_p[512];

    const int k = threadIdx.x;
    const int d = blockIdx.x;
    const float one_minus_decay = 0.01f;

    float cn = g_cluster[k];
    float t = (float)(*counter + 1);
    float debias = 1.0f - powf(0.99f, t);
    float inv_debias = 1.0f / debias;

    float h    = ehc[k];
    float nhc  = h - (h - cn) * one_minus_decay;
    float avgc = nhc * inv_debias;

    red_n[k] = avgc;
    float p = cn * (1.0f / (float)NROWS);
    red_p[k] = (d == 0) ? p * logf(p + 1e-10f) : 0.f;
    __syncthreads();
#pragma unroll
    for (int s = 256; s > 0; s >>= 1) {
        if (k < s) { red_n[k] += red_n[k + s]; red_p[k] += red_p[k + s]; }
        __syncthreads();
    }
    float n_total = red_n[0];
    float smoothed = (avgc + 1e-5f) / (n_total + (float)KCB * 1e-5f) * n_total;

    float dw  = g_dw[d * KCB + k];
    float hd  = ehd[d * KCB + k];
    float nhd = hd - (hd - dw) * one_minus_decay;
    out[OFF_EMB + d * KCB + k] = (nhd * inv_debias) / smoothed;

    if (d == 0 && k == 0) {
        out[OFF_LOSS] = 0.25f * g_loss / (float)((size_t)NROWS * DDIM);
        out[OFF_PERP] = expf(-red_p[0]);
    }
}

// ---------------------------------------------------------------------------
extern "C" void kernel_launch(void* const* d_in, const int* in_sizes, int n_in,
                              void* d_out, int out_size) {
    const float* x       = (const float*)d_in[0];
    const float* emb     = (const float*)d_in[1];
    const float* ehc     = (const float*)d_in[2];
    const float* ehd     = (const float*)d_in[3];
    const int*   counter = (const int*)d_in[4];
    float* out = (float*)d_out;

    cudaFuncSetAttribute(k_main, cudaFuncAttributeMaxDynamicSharedMemorySize,
                         (int)SMEM_SZ);
    cudaFuncSetAttribute(k_fix, cudaFuncAttributeMaxDynamicSharedMemorySize,
                         (int)FX_SZ);
    cudaFuncSetAttribute(k_dw, cudaFuncAttributeMaxDynamicSharedMemorySize,
                         64 * 513 * 4);

    k_prep<<<8, 512>>>(emb);
    k_zero_a<<<32, 512>>>();
    k_zero_b<<<32, 512>>>();
    k_main<<<GRID_MAIN, THREADS, SMEM_SZ>>>(x, emb, out + OFF_Q, out + OFF_IDX);
    k_fix<<<GRID_MAIN, 512, FX_SZ>>>(x, emb, out + OFF_Q, out + OFF_IDX);
    k_dw<<<128, 512, 64 * 513 * 4>>>(x, out + OFF_IDX);
    k_final<<<64, 512>>>(ehc, ehd, counter, out);
}

// round 14
// speedup vs baseline: 1.1852x; 1.0744x over previous
#include <cuda_runtime.h>
#include <cuda_fp16.h>
#include <cstdint>
#include <math.h>

#define NROWS 131072
#define DDIM  64
#define KCB   512
#define TILE_M 128
#define NTILES (NROWS / TILE_M)     // 1024 -> 6.92 tiles/CTA (98.8% balance)
#define GRID_MAIN 148
#define THREADS 512

#define OFF_Q    0
#define OFF_LOSS (NROWS * DDIM)
#define OFF_PERP (OFF_LOSS + 1)
#define OFF_EMB  (OFF_PERP + 1)
#define OFF_IDX  (OFF_EMB + DDIM * KCB)

#define MARGIN 0.15625f
#define MASKH  0xFFFFFE00u
#define KEYBIAS 256.0f
#define SENT 0x7F7FFFFFu

__device__ float g_dw[DDIM * KCB];
__device__ float g_cluster[KCB];
__device__ float g_loss;
__device__ float g_enorm[KCB];
__device__ __align__(16) float g_ecbT[KCB * DDIM];   // codebook transposed [k][d] fp32
__device__ uint2 g_que[NROWS];      // duel queue: {row, i1|(i2<<16)}
__device__ int   g_que2[NROWS];     // rescan queue: row
__device__ int   g_qn, g_qn2;

__device__ __forceinline__ uint32_t pb(uint32_t d) {
    return ((d >> 1) & 3u) * 32u + (d >> 4) * 8u + ((d >> 3) & 1u) * 4u + (d & 1u) * 2u;
}

// smem layout (bytes) for k_main
#define SO_EH    0u          // 65536
#define SO_XH    65536u      // 16384 (128 rows fp16 packed)
#define SO_EN2   81920u      // 2048
#define SO_XN    83968u      // 1024 (2 x 512, double-buffered)
#define SO_TOP   84992u      // 8192 (2 x 4096, double-buffered): [row][half] uint4
#define SO_HIST  93184u      // 2048
#define SMEM_SZ  95232u

__device__ __forceinline__ void mma_f16(float* d, uint32_t a0, uint32_t a1,
                                        uint32_t a2, uint32_t a3,
                                        uint32_t b0, uint32_t b1) {
    asm volatile(
        "mma.sync.aligned.m16n8k16.row.col.f32.f16.f16.f32 "
        "{%0,%1,%2,%3}, {%4,%5,%6,%7}, {%8,%9}, {%0,%1,%2,%3};\n"
        : "+f"(d[0]), "+f"(d[1]), "+f"(d[2]), "+f"(d[3])
        : "r"(a0), "r"(a1), "r"(a2), "r"(a3), "r"(b0), "r"(b1));
}

__device__ __forceinline__ void ins3(uint32_t& m1, uint32_t& m2, uint32_t& m3,
                                     uint32_t k) {
    uint32_t h1 = max(m1, k); m1 = min(m1, k);
    uint32_t h2 = max(m2, h1); m2 = min(m2, h1);
    m3 = min(m3, h2);
}
__device__ __forceinline__ uint32_t mkkey(float dist, uint32_t n) {
    uint32_t r;
    asm("bfi.b32 %0, %1, %2, 0, 9;" : "=r"(r) : "r"(n), "r"(__float_as_uint(dist)));
    return r;
}

__device__ __forceinline__ void do_kb(
    const char* sm, int kb, int g, int q,
    const uint4& A0a, const uint4& A0b, const uint4& A1a, const uint4& A1b,
    const float* s_en2, uint32_t c0, uint32_t c1,
    uint32_t& m11, uint32_t& m12, uint32_t& m13,
    uint32_t& m21, uint32_t& m22, uint32_t& m23)
{
    float acc[8][4];
#pragma unroll
    for (int nt = 0; nt < 8; nt++)
#pragma unroll
        for (int j = 0; j < 4; j++) acc[nt][j] = 0.f;

#pragma unroll
    for (int nt = 0; nt < 8; nt++) {
        uint32_t rowb = (uint32_t)(kb * 64 + nt * 8 + g) * 128u;
        uint4 B0 = *(const uint4*)(sm + SO_EH + rowb + c0);
        uint4 B1 = *(const uint4*)(sm + SO_EH + rowb + c1);
        mma_f16(acc[nt], A0a.x, A1a.x, A0a.y, A1a.y, B0.x, B0.y);
        mma_f16(acc[nt], A0a.z, A1a.z, A0a.w, A1a.w, B0.z, B0.w);
        mma_f16(acc[nt], A0b.x, A1b.x, A0b.y, A1b.y, B1.x, B1.y);
        mma_f16(acc[nt], A0b.z, A1b.z, A0b.w, A1b.w, B1.z, B1.w);
    }
#pragma unroll
    for (int nt = 0; nt < 8; nt++) {
        uint32_t n0 = (uint32_t)(kb * 64 + nt * 8 + q * 2);
        float2 en = *(const float2*)&s_en2[n0];
        uint32_t k0 = mkkey(fmaf(-2.f, acc[nt][0], en.x), n0);
        uint32_t k1 = mkkey(fmaf(-2.f, acc[nt][1], en.y), n0 + 1);
        uint32_t k2 = mkkey(fmaf(-2.f, acc[nt][2], en.x), n0);
        uint32_t k3 = mkkey(fmaf(-2.f, acc[nt][3], en.y), n0 + 1);
        ins3(m11, m12, m13, k0);
        ins3(m11, m12, m13, k1);
        ins3(m21, m22, m23, k2);
        ins3(m21, m22, m23, k3);
    }
}

// ---------------------------------------------------------------------------
// Prep (grid 64 x 512): enorm (blocks 0-7), transposed codebook, zero dw,
// reset queues/scalars (block 63).
// ---------------------------------------------------------------------------
__global__ void k_prep(const float* __restrict__ emb) {
    __shared__ float red[8][64];
    const int t = threadIdx.x, b = blockIdx.x;

    g_dw[b * 512 + t] = 0.f;

    // transposed codebook: 8 codes per block
    {
        int k = b * 8 + (t >> 6), d = t & 63;
        g_ecbT[k * 64 + d] = emb[d * KCB + k];
    }

    if (b < 8) {
        const int kk = t & 63, part = t >> 6;
        const int k = b * 64 + kk;
        float s = 0.f;
#pragma unroll
        for (int j = 0; j < 8; j++) {
            float e = emb[(part * 8 + j) * KCB + k];
            s = fmaf(e, e, s);
        }
        red[part][kk] = s;
        __syncthreads();
        if (t < 64) {
            float tot = red[0][t];
#pragma unroll
            for (int p = 1; p < 8; p++) tot += red[p][t];
            g_enorm[b * 64 + t] = tot;
        }
    }
    if (b == 63) {
        g_cluster[t] = 0.f;
        if (t == 0) { g_loss = 0.f; g_qn = 0; g_qn2 = 0; }
    }
}

// ---------------------------------------------------------------------------
// Main: 512 threads; warps 0-7 scan codes 0-255, warps 8-15 scan 256-511.
// 2 barriers per tile (double-buffered s_top/s_xn).
// ---------------------------------------------------------------------------
__global__ __launch_bounds__(THREADS, 1)
void k_main(const float* __restrict__ x, const float* __restrict__ emb,
            float* __restrict__ out_q, float* __restrict__ out_idx) {
    extern __shared__ __align__(1024) char sm[];
    const int tid  = threadIdx.x;
    const int wid  = tid >> 5;
    const int lane = tid & 31;
    const int g    = lane >> 2;
    const int q    = lane & 3;
    const int half = wid >> 3;       // code half
    const int w8   = wid & 7;

    float* s_en2  = (float*)(sm + SO_EN2);
    float* s_xn   = (float*)(sm + SO_XN);      // [2][128]
    uint4* s_top  = (uint4*)(sm + SO_TOP);     // [2][128][2]
    int*   s_hist = (int*)(sm + SO_HIST);

    for (int i = tid; i < DDIM * KCB; i += THREADS) {
        uint32_t d = (uint32_t)i >> 9, k = (uint32_t)i & 511u;
        uint32_t off = k * 128u + (pb(d) ^ ((k & 7u) * 16u));
        *(__half*)(sm + SO_EH + off) = __float2half_rn(emb[i]);
    }
    s_en2[tid] = g_enorm[tid] + KEYBIAS;
    s_hist[tid] = 0;
    __syncthreads();

    const int r0 = w8 * 16 + g;      // rows 0..127
    const int r1 = r0 + 8;
    const uint32_t c0 = ((uint32_t)q * 32u) ^ ((uint32_t)g * 16u);
    const uint32_t c1 = ((uint32_t)q * 32u + 16u) ^ ((uint32_t)g * 16u);

    float loss_acc = 0.f;
    int buf = 0;

    for (int tile = blockIdx.x; tile < NTILES; tile += gridDim.x) {
        const float* xt = x + (size_t)tile * TILE_M * DDIM;

        // ---- Stage x tile (fp16 packed) + per-row ||x||^2 (buffer `buf`) ----
#pragma unroll
        for (int it = 0; it < 4; it++) {
            int i = it * THREADS + tid;
            float4 v = ((const float4*)xt)[i];
            uint32_t r = (uint32_t)i >> 4, c = ((uint32_t)i & 15u) * 4u;
            uint32_t xw = (r & 7u) * 16u;
            *(__half2*)(sm + SO_XH + r * 128u + (pb(c) ^ xw)) =
                __floats2half2_rn(v.x, v.y);
            *(__half2*)(sm + SO_XH + r * 128u + (pb(c + 2) ^ xw)) =
                __floats2half2_rn(v.z, v.w);
            float pn = fmaf(v.x, v.x, fmaf(v.y, v.y, fmaf(v.z, v.z, v.w * v.w)));
            pn += __shfl_xor_sync(0xffffffffu, pn, 1);
            pn += __shfl_xor_sync(0xffffffffu, pn, 2);
            pn += __shfl_xor_sync(0xffffffffu, pn, 4);
            pn += __shfl_xor_sync(0xffffffffu, pn, 8);
            if ((tid & 15) == 0) s_xn[buf * 128 + r] = pn;
        }
        __syncthreads();   // barrier 1: XH + xn visible

        uint4 A0a = *(const uint4*)(sm + SO_XH + (uint32_t)r0 * 128u + c0);
        uint4 A0b = *(const uint4*)(sm + SO_XH + (uint32_t)r0 * 128u + c1);
        uint4 A1a = *(const uint4*)(sm + SO_XH + (uint32_t)r1 * 128u + c0);
        uint4 A1b = *(const uint4*)(sm + SO_XH + (uint32_t)r1 * 128u + c1);

        uint32_t e11 = SENT, e12 = SENT, e13 = SENT;
        uint32_t o11 = SENT, o12 = SENT, o13 = SENT;
        uint32_t e21 = SENT, e22 = SENT, e23 = SENT;
        uint32_t o21 = SENT, o22 = SENT, o23 = SENT;

#pragma unroll 1
        for (int kbp = 0; kbp < 2; kbp++) {
            do_kb(sm, half * 4 + 2 * kbp,     g, q, A0a, A0b, A1a, A1b,
                  s_en2, c0, c1, e11, e12, e13, e21, e22, e23);
            do_kb(sm, half * 4 + 2 * kbp + 1, g, q, A0a, A0b, A1a, A1b,
                  s_en2, c0, c1, o11, o12, o13, o21, o22, o23);
        }
        ins3(e11, e12, e13, o11); ins3(e11, e12, e13, o12); ins3(e11, e12, e13, o13);
        ins3(e21, e22, e23, o21); ins3(e21, e22, e23, o22); ins3(e21, e22, e23, o23);

#pragma unroll
        for (int o = 1; o <= 2; o <<= 1) {
            uint32_t q1 = __shfl_xor_sync(0xffffffffu, e11, o);
            uint32_t q2 = __shfl_xor_sync(0xffffffffu, e12, o);
            uint32_t q3 = __shfl_xor_sync(0xffffffffu, e13, o);
            ins3(e11, e12, e13, q1);
            ins3(e11, e12, e13, q2);
            ins3(e11, e12, e13, q3);
            q1 = __shfl_xor_sync(0xffffffffu, e21, o);
            q2 = __shfl_xor_sync(0xffffffffu, e22, o);
            q3 = __shfl_xor_sync(0xffffffffu, e23, o);
            ins3(e21, e22, e23, q1);
            ins3(e21, e22, e23, q2);
            ins3(e21, e22, e23, q3);
        }
        if (q == 0) {
            s_top[buf * 256 + ((r0 << 1) | half)] = make_uint4(e11, e12, e13, 0u);
            s_top[buf * 256 + ((r1 << 1) | half)] = make_uint4(e21, e22, e23, 0u);
        }
        __syncthreads();   // barrier 2: s_top visible

        // ---- Phase A: merge halves, emit (fp32 gather) or queue ----
        {
            const int rloc = tid >> 2;
            const int q4   = tid & 3;
            const int row  = tile * TILE_M + rloc;
            uint4 Ka = s_top[buf * 256 + (rloc << 1)];
            uint4 Kb = s_top[buf * 256 + ((rloc << 1) | 1)];
            uint32_t m1 = Ka.x, m2 = Ka.y, m3 = Ka.z;
            ins3(m1, m2, m3, Kb.x);
            ins3(m1, m2, m3, Kb.y);
            ins3(m1, m2, m3, Kb.z);
            float d1 = __uint_as_float(m1 & MASKH);
            float d2 = __uint_as_float(m2 & MASKH);
            float d3 = __uint_as_float(m3 & MASKH);
            int bidx = (int)(m1 & 511u);
            if (d2 - d1 >= MARGIN) {
                if (q4 == 0) {
                    out_idx[row] = (float)bidx;
                    atomicAdd(&s_hist[bidx], 1);
                    loss_acc += d1 - KEYBIAS + s_xn[buf * 128 + rloc]
                              + __uint_as_float(m1 & 0xFF800000u) * 3.0517578125e-05f;
                }
                // emit q: coalesced fp32 gather from transposed codebook
                const float4* ec = (const float4*)(g_ecbT + bidx * DDIM) + q4 * 4;
                float4* oq = (float4*)(out_q + (size_t)row * DDIM) + q4 * 4;
#pragma unroll
                for (int j = 0; j < 4; j++) oq[j] = __ldg(ec + j);
            } else if (q4 == 0) {
                if (d3 - d1 >= MARGIN) {
                    int p = atomicAdd(&g_qn, 1);
                    g_que[p] = make_uint2((unsigned)row,
                                          (m1 & 511u) | ((m2 & 511u) << 16));
                } else {
                    int p = atomicAdd(&g_qn2, 1);
                    g_que2[p] = row;
                }
            }
        }
        buf ^= 1;   // no barrier: next staging targets the other buffers
    }

#pragma unroll
    for (int o = 16; o > 0; o >>= 1)
        loss_acc += __shfl_xor_sync(0xffffffffu, loss_acc, o);
    if (lane == 0) atomicAdd(&g_loss, loss_acc);

    __syncthreads();
    {
        int c = s_hist[tid];
        if (c) atomicAdd(&g_cluster[tid], (float)c);
    }
}

// ---------------------------------------------------------------------------
// Fix: exact fp32 resolution of queued rows (codebook staged in smem).
// ---------------------------------------------------------------------------
#define FX_XROW (64 * 513)               // 64 floats
#define FX_B64  (64 * 513 + 64)          // 2 floats (as ull)
#define FX_SZ   ((64 * 513 + 66) * 4)

__global__ __launch_bounds__(512)
void k_fix(const float* __restrict__ x, const float* __restrict__ emb,
           float* __restrict__ out_q, float* __restrict__ out_idx) {
    extern __shared__ float se[];
    const int tid = threadIdx.x;
    const int wid = tid >> 5;
    const int lane = tid & 31;
    float* xrow = se + FX_XROW;
    unsigned long long* b64 = (unsigned long long*)(se + FX_B64);

    for (int i = tid; i < 64 * 512; i += 512) {
        int d = i >> 9, k = i & 511;
        se[d * 513 + k] = emb[i];
    }
    __syncthreads();

    float loss_acc = 0.f;

    // ---- duels: warp per row ----
    const int qn = g_qn;
    for (int j = blockIdx.x * 16 + wid; j < qn; j += gridDim.x * 16) {
        uint2 e = g_que[j];
        const int row = (int)e.x;
        const int i1 = (int)(e.y & 511u), i2 = (int)((e.y >> 16) & 511u);
        float2 xv = __ldg((const float2*)(x + (size_t)row * DDIM + 2 * lane));
        float e10 = se[(2 * lane) * 513 + i1], e11v = se[(2 * lane + 1) * 513 + i1];
        float e20 = se[(2 * lane) * 513 + i2], e21v = se[(2 * lane + 1) * 513 + i2];
        float a0 = xv.x - e10, a1 = xv.y - e11v;
        float p1 = fmaf(a0, a0, a1 * a1);
        float b0 = xv.x - e20, b1 = xv.y - e21v;
        float p2 = fmaf(b0, b0, b1 * b1);
#pragma unroll
        for (int o = 16; o > 0; o >>= 1) {
            p1 += __shfl_xor_sync(0xffffffffu, p1, o);
            p2 += __shfl_xor_sync(0xffffffffu, p2, o);
        }
        int bidx = i1; float be = p1;
        float q0 = e10, q1 = e11v;
        if (p2 < be || (p2 == be && i2 < bidx)) { be = p2; bidx = i2; q0 = e20; q1 = e21v; }
        *(float2*)(out_q + (size_t)row * DDIM + 2 * lane) = make_float2(q0, q1);
        if (lane == 0) {
            out_idx[row] = (float)bidx;
            atomicAdd(&g_cluster[bidx], 1.f);
            loss_acc += be;
        }
    }

    // ---- rescans: block per row ----
    const int qn2 = g_qn2;
    for (int qi = blockIdx.x; qi < qn2; qi += gridDim.x) {
        const int row = g_que2[qi];
        if (tid < 32) {
            float2 v = ((const float2*)(x + (size_t)row * DDIM))[tid];
            xrow[2 * tid] = v.x;
            xrow[2 * tid + 1] = v.y;
        }
        if (tid == 0) *b64 = 0xFFFFFFFFFFFFFFFFull;
        __syncthreads();
        float a = 0.f;
#pragma unroll 8
        for (int d = 0; d < 64; d++) {
            float t = xrow[d] - se[d * 513 + tid];
            a = fmaf(t, t, a);
        }
        unsigned long long loc =
            (((unsigned long long)__float_as_uint(a)) << 32) | (unsigned)tid;
#pragma unroll
        for (int o = 16; o > 0; o >>= 1) {
            unsigned long long ov = __shfl_xor_sync(0xffffffffu, loc, o);
            loc = min(loc, ov);
        }
        if (lane == 0) atomicMin(b64, loc);
        __syncthreads();
        const unsigned long long win = *b64;
        const int bidx = (int)(win & 511u);
        if (tid < 64)
            out_q[(size_t)row * DDIM + tid] = se[tid * 513 + bidx];
        if (tid == 0) {
            out_idx[row] = (float)bidx;
            atomicAdd(&g_cluster[bidx], 1.f);
            loss_acc += __uint_as_float((uint32_t)(win >> 32));
        }
        __syncthreads();
    }

#pragma unroll
    for (int o = 16; o > 0; o >>= 1)
        loss_acc += __shfl_xor_sync(0xffffffffu, loss_acc, o);
    if (lane == 0 && loss_acc != 0.f) atomicAdd(&g_loss, loss_acc);
}

// ---------------------------------------------------------------------------
__global__ __launch_bounds__(512)
void k_dw(const float* __restrict__ x, const float* __restrict__ idxf) {
    extern __shared__ float sdw[];          // [64][513]
    const int t = threadIdx.x;
    const int d = t & 63;
    const int rs = t >> 6;
    const int base = blockIdx.x * 1024;
    for (int i = t; i < 64 * 513; i += 512) sdw[i] = 0.f;
    __syncthreads();
#pragma unroll 1
    for (int j0 = 0; j0 < 1024; j0 += 32) {
        float xv[4]; int cd[4];
#pragma unroll
        for (int u = 0; u < 4; u++) {
            int r = base + j0 + rs * 4 + u;
            cd[u] = (int)__ldg(&idxf[r]);
            xv[u] = __ldg(&x[(size_t)r * 64 + d]);
        }
        float s = xv[0]; int c = cd[0];
#pragma unroll
        for (int u = 1; u < 4; u++) {
            if (cd[u] == c) s += xv[u];
            else { atomicAdd(&sdw[d * 513 + c], s); c = cd[u]; s = xv[u]; }
        }
        atomicAdd(&sdw[d * 513 + c], s);
    }
    __syncthreads();
    for (int i = t; i < 64 * 512; i += 512) {
        int dd = i >> 9, k = i & 511;
        float v = sdw[dd * 513 + k];
        if (v != 0.f) atomicAdd(&g_dw[i], v);
    }
}

// ---------------------------------------------------------------------------
__global__ void k_final(const float* __restrict__ ehc,
                        const float* __restrict__ ehd,
                        const int* __restrict__ counter,
                        float* __restrict__ out) {
    __shared__ float red_n[512];
    __shared__ float red_p[512];

    const int k = threadIdx.x;
    const int d = blockIdx.x;
    const float one_minus_decay = 0.01f;

    float cn = g_cluster[k];
    float t = (float)(*counter + 1);
    float debias = 1.0f - powf(0.99f, t);
    float inv_debias = 1.0f / debias;

    float h    = ehc[k];
    float nhc  = h - (h - cn) * one_minus_decay;
    float avgc = nhc * inv_debias;

    red_n[k] = avgc;
    float p = cn * (1.0f / (float)NROWS);
    red_p[k] = (d == 0) ? p * logf(p + 1e-10f) : 0.f;
    __syncthreads();
#pragma unroll
    for (int s = 256; s > 0; s >>= 1) {
        if (k < s) { red_n[k] += red_n[k + s]; red_p[k] += red_p[k + s]; }
        __syncthreads();
    }
    float n_total = red_n[0];
    float smoothed = (avgc + 1e-5f) / (n_total + (float)KCB * 1e-5f) * n_total;

    float dw  = g_dw[d * KCB + k];
    float hd  = ehd[d * KCB + k];
    float nhd = hd - (hd - dw) * one_minus_decay;
    out[OFF_EMB + d * KCB + k] = (nhd * inv_debias) / smoothed;

    if (d == 0 && k == 0) {
        out[OFF_LOSS] = 0.25f * g_loss / (float)((size_t)NROWS * DDIM);
        out[OFF_PERP] = expf(-red_p[0]);
    }
}

// ---------------------------------------------------------------------------
extern "C" void kernel_launch(void* const* d_in, const int* in_sizes, int n_in,
                              void* d_out, int out_size) {
    const float* x       = (const float*)d_in[0];
    const float* emb     = (const float*)d_in[1];
    const float* ehc     = (const float*)d_in[2];
    const float* ehd     = (const float*)d_in[3];
    const int*   counter = (const int*)d_in[4];
    float* out = (float*)d_out;

    cudaFuncSetAttribute(k_main, cudaFuncAttributeMaxDynamicSharedMemorySize,
                         (int)SMEM_SZ);
    cudaFuncSetAttribute(k_fix, cudaFuncAttributeMaxDynamicSharedMemorySize,
                         (int)FX_SZ);
    cudaFuncSetAttribute(k_dw, cudaFuncAttributeMaxDynamicSharedMemorySize,
                         64 * 513 * 4);

    k_prep<<<64, 512>>>(emb);
    k_main<<<GRID_MAIN, THREADS, SMEM_SZ>>>(x, emb, out + OFF_Q, out + OFF_IDX);
    k_fix<<<GRID_MAIN, 512, FX_SZ>>>(x, emb, out + OFF_Q, out + OFF_IDX);
    k_dw<<<128, 512, 64 * 513 * 4>>>(x, out + OFF_IDX);
    k_final<<<64, 512>>>(ehc, ehd, counter, out);
}